// round 5
// baseline (speedup 1.0000x reference)
#include <cuda_runtime.h>
#include <cstdint>

#define BB        4
#define NPTS      4096
#define TPB       512
#define QPT       8                       // queries register-cached per thread
#define QPB       (TPB * QPT)             // 4096 queries per block = one (dir,b)
#define NSLICE    16                      // target slices
#define SLICE_PTS (NPTS / NSLICE)         // 256 targets per slice
#define SLICE_PR  (SLICE_PTS / 2)         // 128 target pairs in smem (4 KB)
#define NQ_TOTAL  (2 * BB * NPTS)         // 32768 query slots
#define NQTILE    (NQ_TOTAL / QPB)        // 8  (= dir*4 + b)
#define NBLK1     (NQTILE * NSLICE)       // 128 blocks, 1/SM, 4 warps/SMSP
#define RTPB      256
#define NBLK2     (NQ_TOTAL / 4 / RTPB)   // 32 reduce blocks, 1 float4/thread

__device__ float g_min[NSLICE][NQ_TOTAL];   // 2 MB, every entry written
__device__ float g_part[NBLK2];
__device__ int   g_ticket;                  // zero-init; last block resets it

__device__ __forceinline__ uint64_t pk2(float lo, float hi) {
    uint64_t r;
    asm("mov.b64 %0, {%1, %2};" : "=l"(r) : "f"(lo), "f"(hi));
    return r;
}
__device__ __forceinline__ uint64_t fma2(uint64_t a, uint64_t b, uint64_t c) {
    uint64_t d;
    asm("fma.rn.f32x2 %0, %1, %2, %3;" : "=l"(d) : "l"(a), "l"(b), "l"(c));
    return d;
}
__device__ __forceinline__ void unpk(uint64_t v, float& lo, float& hi) {
    asm("mov.b64 {%0, %1}, %2;" : "=f"(lo), "=f"(hi) : "l"(v));
}

// Block = (4096-query tile = one (dir,batch)) x (256-target slice).
// Targets pair-interleaved in smem: sA[p]={x0,x1,y0,y1}, sB[p]={z0,z1,w0,w1}, w=|t|^2.
// Per thread: 8 queries in registers -> per 2-target step: 2 LDS.128 + 24 FFMA2 + 16 FMNMX.
// Issue count (~42/step/warp) is well under the FMA-pipe cycle cost -> FMA-bound.
__global__ void __launch_bounds__(TPB)
chamfer_stage1(const float* __restrict__ src, const float* __restrict__ tgt)
{
    __shared__ float4 sA[SLICE_PR];
    __shared__ float4 sB[SLICE_PR];

    int qtile = blockIdx.x >> 4;          // 0..7 = dir*4 + b
    int slice = blockIdx.x & 15;
    int dir   = qtile >> 2;
    int b     = qtile & 3;

    const float* qb = (dir ? tgt : src) + (size_t)b * NPTS * 3;
    const float* db = (dir ? src : tgt) + ((size_t)b * NPTS + slice * SLICE_PTS) * 3;

    if (threadIdx.x < SLICE_PR) {
        int p = threadIdx.x;
        const float* t = db + 6 * p;
        float x0 = t[0], y0 = t[1], z0 = t[2];
        float x1 = t[3], y1 = t[4], z1 = t[5];
        sA[p] = make_float4(x0, x1, y0, y1);
        sB[p] = make_float4(z0, z1,
                            fmaf(x0, x0, fmaf(y0, y0, z0 * z0)),
                            fmaf(x1, x1, fmaf(y1, y1, z1 * z1)));
    }

    uint64_t SX[QPT], SY[QPT], SZ[QPT];
    float x2[QPT], m0[QPT], m1[QPT];
    #pragma unroll
    for (int k = 0; k < QPT; k++) {
        int qi = threadIdx.x + k * TPB;
        float sx = qb[3 * qi], sy = qb[3 * qi + 1], sz = qb[3 * qi + 2];
        x2[k] = fmaf(sx, sx, fmaf(sy, sy, sz * sz));
        SX[k] = pk2(-2.f * sx, -2.f * sx);
        SY[k] = pk2(-2.f * sy, -2.f * sy);
        SZ[k] = pk2(-2.f * sz, -2.f * sz);
        m0[k] = 3.4e38f; m1[k] = 3.4e38f;
    }
    __syncthreads();

    const ulonglong2* A  = (const ulonglong2*)sA;   // {x0,x1},{y0,y1}
    const ulonglong2* Bm = (const ulonglong2*)sB;   // {z0,z1},{w0,w1}

    #pragma unroll 4
    for (int p = 0; p < SLICE_PR; p++) {
        ulonglong2 a  = A[p];
        ulonglong2 bb = Bm[p];
        #pragma unroll
        for (int k = 0; k < QPT; k++) {
            uint64_t v = fma2(SX[k], a.x, fma2(SY[k], a.y, fma2(SZ[k], bb.x, bb.y)));
            float v0, v1;
            unpk(v, v0, v1);
            m0[k] = fminf(m0[k], v0);
            m1[k] = fminf(m1[k], v1);
        }
    }

    int gq0 = qtile * QPB + threadIdx.x;
    #pragma unroll
    for (int k = 0; k < QPT; k++)
        g_min[slice][gq0 + k * TPB] = fminf(m0[k], m1[k]) + x2[k];
}

// 32 blocks: min over 16 slices + per-block partial sum; last block (ticket)
// merges the 32 partials with a LANE-PARALLEL load + shfl tree (fixed order,
// deterministic) instead of a serial dependent-load chain.
__global__ void __launch_bounds__(RTPB)
chamfer_reduce(float* __restrict__ out)
{
    int t   = threadIdx.x;
    int idx = blockIdx.x * RTPB + t;          // float4 index, 4 queries

    float4 m = ((const float4*)g_min[0])[idx];
    #pragma unroll
    for (int s = 1; s < NSLICE; s++) {
        float4 a = ((const float4*)g_min[s])[idx];
        m.x = fminf(m.x, a.x); m.y = fminf(m.y, a.y);
        m.z = fminf(m.z, a.z); m.w = fminf(m.w, a.w);
    }
    float sum = (m.x + m.y) + (m.z + m.w);

    #pragma unroll
    for (int off = 16; off > 0; off >>= 1)
        sum += __shfl_down_sync(0xFFFFFFFFu, sum, off);

    __shared__ float ws[RTPB / 32];
    if ((t & 31) == 0) ws[t >> 5] = sum;
    __syncthreads();
    if (t == 0) {
        float s = ws[0];
        #pragma unroll
        for (int i = 1; i < RTPB / 32; i++) s += ws[i];
        g_part[blockIdx.x] = s;
    }
    __syncthreads();

    __shared__ int amLast;
    if (t == 0) {
        __threadfence();
        int prev = atomicAdd(&g_ticket, 1);
        amLast = (prev == NBLK2 - 1);
    }
    __syncthreads();

    if (amLast && t < 32) {
        float p = (t < NBLK2) ? *((volatile float*)&g_part[t]) : 0.f;
        #pragma unroll
        for (int off = 16; off > 0; off >>= 1)
            p += __shfl_down_sync(0xFFFFFFFFu, p, off);
        if (t == 0) {
            out[0] = p * (1.0f / (float)(BB * NPTS));
            g_ticket = 0;                     // reset for next graph replay
        }
    }
}

extern "C" void kernel_launch(void* const* d_in, const int* in_sizes, int n_in,
                              void* d_out, int out_size)
{
    const float* src = (const float*)d_in[0];
    const float* tgt = (const float*)d_in[1];
    float* out = (float*)d_out;

    chamfer_stage1<<<NBLK1, TPB>>>(src, tgt);
    chamfer_reduce<<<NBLK2, RTPB>>>(out);
}

// round 6
// speedup vs baseline: 1.0287x; 1.0287x over previous
#include <cuda_runtime.h>
#include <cstdint>

#define BB        4
#define NPTS      4096
#define TPB       512
#define QPT       8                       // queries register-cached per thread
#define QPB       (TPB * QPT)             // 4096 queries per block = one (dir,b)
#define NSLICE    16                      // target slices
#define SLICE_PTS (NPTS / NSLICE)         // 256 targets per slice
#define SLICE_PR  (SLICE_PTS / 2)         // 128 target pairs in smem (4 KB)
#define NQ_TOTAL  (2 * BB * NPTS)         // 32768 query slots
#define NQTILE    (NQ_TOTAL / QPB)        // 8  (= dir*4 + b)
#define NBLK1     (NQTILE * NSLICE)       // 128 blocks, 1/SM, 4 warps/SMSP

// Per-query running min, stored as float BIT PATTERN (all distances > 0, so
// unsigned order == float order). memset to 0x7F7F7F7F (3.39e38) each launch.
// atomicMin is exact and idempotent -> result is bit-deterministic.
__device__ unsigned g_minq[NQ_TOTAL];     // 128 KB
__device__ int      g_ticket;             // zero-init; last block resets it

__device__ __forceinline__ uint64_t pk2(float lo, float hi) {
    uint64_t r;
    asm("mov.b64 %0, {%1, %2};" : "=l"(r) : "f"(lo), "f"(hi));
    return r;
}
__device__ __forceinline__ uint64_t fma2(uint64_t a, uint64_t b, uint64_t c) {
    uint64_t d;
    asm("fma.rn.f32x2 %0, %1, %2, %3;" : "=l"(d) : "l"(a), "l"(b), "l"(c));
    return d;
}
__device__ __forceinline__ void unpk(uint64_t v, float& lo, float& hi) {
    asm("mov.b64 {%0, %1}, %2;" : "=f"(lo), "=f"(hi) : "l"(v));
}

// Block = (4096-query tile = one (dir,batch)) x (256-target slice).
// Targets pair-interleaved in smem: sA[p]={x0,x1,y0,y1}, sB[p]={z0,z1,w0,w1}, w=|t|^2.
// Mainloop: per 2-target step per warp: 2 LDS.128 + 24 FFMA2 + 16 FMNMX.
// Epilogue: REDG.MIN per query; LAST block (ticket) sums g_minq and writes out.
__global__ void __launch_bounds__(TPB)
chamfer_fused(const float* __restrict__ src, const float* __restrict__ tgt,
              float* __restrict__ out)
{
    __shared__ float4 sA[SLICE_PR];
    __shared__ float4 sB[SLICE_PR];

    int qtile = blockIdx.x >> 4;          // 0..7 = dir*4 + b
    int slice = blockIdx.x & 15;
    int dir   = qtile >> 2;
    int b     = qtile & 3;

    const float* qb = (dir ? tgt : src) + (size_t)b * NPTS * 3;
    const float* db = (dir ? src : tgt) + ((size_t)b * NPTS + slice * SLICE_PTS) * 3;

    if (threadIdx.x < SLICE_PR) {
        int p = threadIdx.x;
        const float* t = db + 6 * p;
        float x0 = t[0], y0 = t[1], z0 = t[2];
        float x1 = t[3], y1 = t[4], z1 = t[5];
        sA[p] = make_float4(x0, x1, y0, y1);
        sB[p] = make_float4(z0, z1,
                            fmaf(x0, x0, fmaf(y0, y0, z0 * z0)),
                            fmaf(x1, x1, fmaf(y1, y1, z1 * z1)));
    }

    uint64_t SX[QPT], SY[QPT], SZ[QPT];
    float x2[QPT], m0[QPT], m1[QPT];
    #pragma unroll
    for (int k = 0; k < QPT; k++) {
        int qi = threadIdx.x + k * TPB;
        float sx = qb[3 * qi], sy = qb[3 * qi + 1], sz = qb[3 * qi + 2];
        x2[k] = fmaf(sx, sx, fmaf(sy, sy, sz * sz));
        SX[k] = pk2(-2.f * sx, -2.f * sx);
        SY[k] = pk2(-2.f * sy, -2.f * sy);
        SZ[k] = pk2(-2.f * sz, -2.f * sz);
        m0[k] = 3.4e38f; m1[k] = 3.4e38f;
    }
    __syncthreads();

    const ulonglong2* A  = (const ulonglong2*)sA;   // {x0,x1},{y0,y1}
    const ulonglong2* Bm = (const ulonglong2*)sB;   // {z0,z1},{w0,w1}

    #pragma unroll 4
    for (int p = 0; p < SLICE_PR; p++) {
        ulonglong2 a  = A[p];
        ulonglong2 bb = Bm[p];
        #pragma unroll
        for (int k = 0; k < QPT; k++) {
            uint64_t v = fma2(SX[k], a.x, fma2(SY[k], a.y, fma2(SZ[k], bb.x, bb.y)));
            float v0, v1;
            unpk(v, v0, v1);
            m0[k] = fminf(m0[k], v0);
            m1[k] = fminf(m1[k], v1);
        }
    }

    // Cross-slice combine: REDG.MIN on float bits (positive -> order-preserving).
    int gq0 = qtile * QPB + threadIdx.x;
    #pragma unroll
    for (int k = 0; k < QPT; k++) {
        float val = fminf(m0[k], m1[k]) + x2[k];
        atomicMin(&g_minq[gq0 + k * TPB], __float_as_uint(val));
    }

    // Ticket: last block to finish performs the final sum.
    __threadfence();
    __syncthreads();
    __shared__ int amLast;
    if (threadIdx.x == 0) {
        int prev = atomicAdd(&g_ticket, 1);
        amLast = (prev == NBLK1 - 1);
    }
    __syncthreads();
    if (!amLast) return;

    __threadfence();   // acquire: make all blocks' REDG.MINs visible
    float sum = 0.f;
    const uint4* G = (const uint4*)g_minq;            // 8192 uint4
    #pragma unroll
    for (int j = 0; j < NQ_TOTAL / 4 / TPB; j++) {    // 16 iters
        uint4 u = __ldcg(&G[threadIdx.x + j * TPB]);  // bypass L1 (atomics live in L2)
        sum += (__uint_as_float(u.x) + __uint_as_float(u.y))
             + (__uint_as_float(u.z) + __uint_as_float(u.w));
    }
    #pragma unroll
    for (int off = 16; off > 0; off >>= 1)
        sum += __shfl_down_sync(0xFFFFFFFFu, sum, off);

    __shared__ float ws[TPB / 32];
    if ((threadIdx.x & 31) == 0) ws[threadIdx.x >> 5] = sum;
    __syncthreads();
    if (threadIdx.x == 0) {
        float tot = 0.f;
        #pragma unroll
        for (int i = 0; i < TPB / 32; i++) tot += ws[i];   // fixed order
        out[0] = tot * (1.0f / (float)(BB * NPTS));
        g_ticket = 0;                                      // reset for next replay
    }
}

extern "C" void kernel_launch(void* const* d_in, const int* in_sizes, int n_in,
                              void* d_out, int out_size)
{
    const float* src = (const float*)d_in[0];
    const float* tgt = (const float*)d_in[1];
    float* out = (float*)d_out;

    void* minq_addr = nullptr;
    cudaGetSymbolAddress(&minq_addr, g_minq);
    // 0x7F7F7F7F = 3.39e38f sentinel, far above any real squared distance.
    cudaMemsetAsync(minq_addr, 0x7F, NQ_TOTAL * sizeof(unsigned));

    chamfer_fused<<<NBLK1, TPB>>>(src, tgt, out);
}

// round 7
// speedup vs baseline: 1.0297x; 1.0010x over previous
#include <cuda_runtime.h>
#include <cstdint>

#define BB        4
#define NPTS      4096
#define TPB       512
#define QPT       8                       // queries per thread (4 packed pairs)
#define QPB       (TPB * QPT)             // 4096 queries per block = one (dir,b)
#define NSLICE    16                      // target slices
#define SLICE_PTS (NPTS / NSLICE)         // 256 targets per slice
#define NQ_TOTAL  (2 * BB * NPTS)         // 32768 query slots
#define NQTILE    (NQ_TOTAL / QPB)        // 8  (= dir*4 + b)
#define NBLK1     (NQTILE * NSLICE)       // 128 blocks, 1/SM, 4 warps/SMSP

// Per-query running min as float BIT PATTERN (distances > 0 -> uint order ==
// float order). memset to 0x7F7F7F7F (3.39e38) each launch. atomicMin is exact
// and idempotent -> bit-deterministic.
__device__ unsigned g_minq[NQ_TOTAL];     // 128 KB
__device__ int      g_ticket;             // zero-init; last block resets it

__device__ __forceinline__ uint64_t pk2(float lo, float hi) {
    uint64_t r;
    asm("mov.b64 %0, {%1, %2};" : "=l"(r) : "f"(lo), "f"(hi));
    return r;
}
__device__ __forceinline__ uint64_t fma2(uint64_t a, uint64_t b, uint64_t c) {
    uint64_t d;
    asm("fma.rn.f32x2 %0, %1, %2, %3;" : "=l"(d) : "l"(a), "l"(b), "l"(c));
    return d;
}
__device__ __forceinline__ void unpk(uint64_t v, float& lo, float& hi) {
    asm("mov.b64 {%0, %1}, %2;" : "=f"(lo), "=f"(hi) : "l"(v));
}

// Block = (4096-query tile = one (dir,batch)) x (256-target slice).
// Targets stored BROADCAST-DUPLICATED in smem: sT1[p]={x,x,y,y}, sT2[p]={z,z,w,w}
// (w=|t|^2), so the duplication costs smem, not registers. Queries are packed
// in PAIRS in registers: QX[j]={-2sx_a,-2sx_b}. 8 queries = 24 persistent regs.
// Per target step per thread: 2 LDS.128 + 12 FFMA2 + 8 FMNMX (8 distances).
__global__ void __launch_bounds__(TPB, 1)
chamfer_fused(const float* __restrict__ src, const float* __restrict__ tgt,
              float* __restrict__ out)
{
    __shared__ float4 sT1[SLICE_PTS];   // {tx,tx,ty,ty}
    __shared__ float4 sT2[SLICE_PTS];   // {tz,tz, w, w}

    int qtile = blockIdx.x >> 4;          // 0..7 = dir*4 + b
    int slice = blockIdx.x & 15;
    int dir   = qtile >> 2;
    int b     = qtile & 3;

    const float* qb = (dir ? tgt : src) + (size_t)b * NPTS * 3;
    const float* db = (dir ? src : tgt) + ((size_t)b * NPTS + slice * SLICE_PTS) * 3;

    if (threadIdx.x < SLICE_PTS) {
        int p = threadIdx.x;
        float x = db[3 * p], y = db[3 * p + 1], z = db[3 * p + 2];
        float w = fmaf(x, x, fmaf(y, y, z * z));
        sT1[p] = make_float4(x, x, y, y);
        sT2[p] = make_float4(z, z, w, w);
    }

    // 4 packed query pairs: pair j = queries (tid + 2j*TPB, tid + (2j+1)*TPB).
    uint64_t QX[4], QY[4], QZ[4];
    float x2lo[4], x2hi[4], mlo[4], mhi[4];
    #pragma unroll
    for (int j = 0; j < 4; j++) {
        int qa = threadIdx.x + (2 * j) * TPB;
        int qc = threadIdx.x + (2 * j + 1) * TPB;
        float ax = qb[3 * qa], ay = qb[3 * qa + 1], az = qb[3 * qa + 2];
        float cx = qb[3 * qc], cy = qb[3 * qc + 1], cz = qb[3 * qc + 2];
        x2lo[j] = fmaf(ax, ax, fmaf(ay, ay, az * az));
        x2hi[j] = fmaf(cx, cx, fmaf(cy, cy, cz * cz));
        QX[j] = pk2(-2.f * ax, -2.f * cx);
        QY[j] = pk2(-2.f * ay, -2.f * cy);
        QZ[j] = pk2(-2.f * az, -2.f * cz);
        mlo[j] = 3.4e38f; mhi[j] = 3.4e38f;
    }
    __syncthreads();

    const ulonglong2* T1 = (const ulonglong2*)sT1;  // .x={tx,tx} .y={ty,ty}
    const ulonglong2* T2 = (const ulonglong2*)sT2;  // .x={tz,tz} .y={ w, w}

    #pragma unroll 4
    for (int p = 0; p < SLICE_PTS; p++) {
        ulonglong2 t1 = T1[p];
        ulonglong2 t2 = T2[p];
        #pragma unroll
        for (int j = 0; j < 4; j++) {
            uint64_t v = fma2(QX[j], t1.x, fma2(QY[j], t1.y, fma2(QZ[j], t2.x, t2.y)));
            float v0, v1;
            unpk(v, v0, v1);
            mlo[j] = fminf(mlo[j], v0);
            mhi[j] = fminf(mhi[j], v1);
        }
    }

    // Cross-slice combine: REDG.MIN on float bits.
    int gq0 = qtile * QPB + threadIdx.x;
    #pragma unroll
    for (int j = 0; j < 4; j++) {
        atomicMin(&g_minq[gq0 + (2 * j)     * TPB], __float_as_uint(mlo[j] + x2lo[j]));
        atomicMin(&g_minq[gq0 + (2 * j + 1) * TPB], __float_as_uint(mhi[j] + x2hi[j]));
    }

    // Ticket: last block performs the final sum.
    __threadfence();
    __syncthreads();
    __shared__ int amLast;
    if (threadIdx.x == 0) {
        int prev = atomicAdd(&g_ticket, 1);
        amLast = (prev == NBLK1 - 1);
    }
    __syncthreads();
    if (!amLast) return;

    __threadfence();   // acquire: all blocks' REDG.MINs visible
    float sum = 0.f;
    const uint4* G = (const uint4*)g_minq;            // 8192 uint4
    #pragma unroll
    for (int jj = 0; jj < NQ_TOTAL / 4 / TPB; jj++) { // 16 iters
        uint4 u = __ldcg(&G[threadIdx.x + jj * TPB]); // bypass L1 (atomics in L2)
        sum += (__uint_as_float(u.x) + __uint_as_float(u.y))
             + (__uint_as_float(u.z) + __uint_as_float(u.w));
    }
    #pragma unroll
    for (int off = 16; off > 0; off >>= 1)
        sum += __shfl_down_sync(0xFFFFFFFFu, sum, off);

    __shared__ float ws[TPB / 32];
    if ((threadIdx.x & 31) == 0) ws[threadIdx.x >> 5] = sum;
    __syncthreads();
    if (threadIdx.x == 0) {
        float tot = 0.f;
        #pragma unroll
        for (int i = 0; i < TPB / 32; i++) tot += ws[i];   // fixed order
        out[0] = tot * (1.0f / (float)(BB * NPTS));
        g_ticket = 0;                                      // reset for next replay
    }
}

extern "C" void kernel_launch(void* const* d_in, const int* in_sizes, int n_in,
                              void* d_out, int out_size)
{
    const float* src = (const float*)d_in[0];
    const float* tgt = (const float*)d_in[1];
    float* out = (float*)d_out;

    void* minq_addr = nullptr;
    cudaGetSymbolAddress(&minq_addr, g_minq);
    // 0x7F7F7F7F = 3.39e38f sentinel, far above any real squared distance.
    cudaMemsetAsync(minq_addr, 0x7F, NQ_TOTAL * sizeof(unsigned));

    chamfer_fused<<<NBLK1, TPB>>>(src, tgt, out);
}